// round 17
// baseline (speedup 1.0000x reference)
#include <cuda_runtime.h>

#define NN 100000
#define NE 1600000
#define D 48
#define NCONVS 6
#define NG 1000

#define EPC 256     // edges per CTA (128 threads, 2 consecutive edges/thread)
#define XSTRIDE 49  // padded x row stride in floats (odd -> conflict-free scalar LDS)

#define SCAN_BLK 1024
#define NSCAN_BLKS ((NN + SCAN_BLK - 1) / SCAN_BLK)   // 98

typedef unsigned long long u64;

// Scratch state (no allocation allowed).
__device__ float4 g_h[NN * 12];
__device__ float4 g_agg[NN * 12];
// counting-sort scratch
__device__ int g_cnt[NN];
__device__ int g_scan[NN];
__device__ int g_bsum[NSCAN_BLKS];
__device__ int g_woff[NN];
__device__ int g_ssrc[NE];
__device__ int g_sdst[NE];
// packed per-layer weights: [l][0:4704) message MLP, [4704:9408) update MLP
// (each MLP: [0:2304) w1, [2304:4608) w2, [4608:4656) b1, [4656:4704) b2)
__device__ float g_pack[NCONVS * 9408];
// packed readout weights: [0:2304) rw1, [2304:2352) rb1, [2352:2400) rw2, [2400] rb2
__device__ float g_packr[2401];

// Single constant bank: per layer holds message+update; after the conv loop it
// is overwritten with the readout weights (stream-ordered, so race-free).
__constant__ float c_all[9408];

// ---------- packed f32x2 helpers ----------
__device__ __forceinline__ u64 fma2(u64 a, u64 b, u64 c) {
    u64 d;
    asm("fma.rn.f32x2 %0, %1, %2, %3;" : "=l"(d) : "l"(a), "l"(b), "l"(c));
    return d;
}
__device__ __forceinline__ u64 add2(u64 a, u64 b) {
    u64 d;
    asm("add.rn.f32x2 %0, %1, %2;" : "=l"(d) : "l"(a), "l"(b));
    return d;
}
__device__ __forceinline__ u64 pack2(float lo, float hi) {
    u64 r;
    asm("mov.b64 %0, {%1, %2};" : "=l"(r) : "f"(lo), "f"(hi));
    return r;
}
__device__ __forceinline__ float2 unpack2(u64 v) {
    float2 f;
    asm("mov.b64 {%0, %1}, %2;" : "=f"(f.x), "=f"(f.y) : "l"(v));
    return f;
}

// ---------- weight packing ----------
__global__ void pack_weights_kernel(const float* __restrict__ mw1, const float* __restrict__ mb1,
                                    const float* __restrict__ mw2, const float* __restrict__ mb2,
                                    const float* __restrict__ uw1, const float* __restrict__ ub1,
                                    const float* __restrict__ uw2, const float* __restrict__ ub2,
                                    const float* __restrict__ rw1, const float* __restrict__ rb1,
                                    const float* __restrict__ rw2, const float* __restrict__ rb2) {
    int i = blockIdx.x * blockDim.x + threadIdx.x;   // over NCONVS*9408
    if (i < NCONVS * 9408) {
        int l = i / 9408;
        int o = i - l * 9408;
        const float* w1 = (o < 4704) ? mw1 : uw1;
        const float* w2 = (o < 4704) ? mw2 : uw2;
        const float* b1 = (o < 4704) ? mb1 : ub1;
        const float* b2 = (o < 4704) ? mb2 : ub2;
        int p = (o < 4704) ? o : o - 4704;
        float v;
        if (p < 2304) v = w1[l * 2304 + p];
        else if (p < 4608) v = w2[l * 2304 + p - 2304];
        else if (p < 4656) v = b1[l * D + p - 4608];
        else v = b2[l * D + p - 4656];
        g_pack[i] = v;
    }
    if (i < 2401) {
        float v;
        if (i < 2304) v = rw1[i];
        else if (i < 2352) v = rb1[i - 2304];
        else if (i < 2400) v = rw2[i - 2352];
        else v = rb2[0];
        g_packr[i] = v;
    }
}

// ---------- counting sort by dst ----------
__global__ void zero_cnt_kernel() {
    int i = blockIdx.x * blockDim.x + threadIdx.x;
    if (i < NN) g_cnt[i] = 0;
}
__global__ void hist_kernel(const int* __restrict__ edge) {
    int e = blockIdx.x * blockDim.x + threadIdx.x;
    if (e < NE) atomicAdd(&g_cnt[edge[NE + e]], 1);
}
__global__ void scan1_kernel() {
    __shared__ int sh[SCAN_BLK];
    int tid = threadIdx.x;
    int i = blockIdx.x * SCAN_BLK + tid;
    int v = (i < NN) ? g_cnt[i] : 0;
    sh[tid] = v;
    __syncthreads();
#pragma unroll
    for (int o = 1; o < SCAN_BLK; o <<= 1) {
        int t = (tid >= o) ? sh[tid - o] : 0;
        __syncthreads();
        sh[tid] += t;
        __syncthreads();
    }
    if (i < NN) g_scan[i] = sh[tid];
    if (tid == SCAN_BLK - 1) g_bsum[blockIdx.x] = sh[tid];
}
__global__ void scan2_kernel() {
    if (threadIdx.x == 0 && blockIdx.x == 0) {
        int acc = 0;
        for (int b = 0; b < NSCAN_BLKS; b++) {
            int t = g_bsum[b];
            g_bsum[b] = acc;
            acc += t;
        }
    }
}
__global__ void scan3_kernel() {
    int i = blockIdx.x * blockDim.x + threadIdx.x;
    if (i < NN) g_woff[i] = g_scan[i] - g_cnt[i] + g_bsum[i / SCAN_BLK];
}
__global__ void scatter_sort_kernel(const int* __restrict__ edge) {
    int e = blockIdx.x * blockDim.x + threadIdx.x;
    if (e >= NE) return;
    int d = edge[NE + e];
    int pos = atomicAdd(&g_woff[d], 1);
    g_ssrc[pos] = edge[e];
    g_sdst[pos] = d;
}

// ---------- dual-row full-width GEMM: x from SMEM, W from __constant__ ----------
__device__ __forceinline__ void gemm48_dual_c(const float* __restrict__ x0,
                                              const float* __restrict__ x1,
                                              u64 acc0[24], u64 acc1[24],
                                              const float (&cw)[9408],
                                              int wofs, int bofs) {
#pragma unroll
    for (int j = 0; j < 24; j++) {
        u64 b = *reinterpret_cast<const u64*>(&cw[bofs + 2 * j]);
        acc0[j] = b;
        acc1[j] = b;
    }
#pragma unroll 4
    for (int k = 0; k < D; k++) {
        float a0 = x0[k];
        float a1 = x1[k];
        u64 xk0 = pack2(a0, a0);
        u64 xk1 = pack2(a1, a1);
        const ulonglong2* wr = reinterpret_cast<const ulonglong2*>(&cw[wofs + k * D]);
#pragma unroll
        for (int jj = 0; jj < 12; jj++) {
            ulonglong2 w = wr[jj];
            acc0[2 * jj]     = fma2(xk0, w.x, acc0[2 * jj]);
            acc0[2 * jj + 1] = fma2(xk0, w.y, acc0[2 * jj + 1]);
            acc1[2 * jj]     = fma2(xk1, w.x, acc1[2 * jj]);
            acc1[2 * jj + 1] = fma2(xk1, w.y, acc1[2 * jj + 1]);
        }
    }
}

// relu accumulators back into own smem x rows (same-thread, no sync needed)
__device__ __forceinline__ void relu_writeback(float* x, const u64 a[24]) {
#pragma unroll
    for (int j = 0; j < 24; j++) {
        float2 v = unpack2(a[j]);
        x[2 * j]     = fmaxf(v.x, 0.f);
        x[2 * j + 1] = fmaxf(v.y, 0.f);
    }
}

// ---------- kernels ----------

__global__ void embed_kernel(const int* __restrict__ an, const float4* __restrict__ emb4) {
    int i = blockIdx.x * blockDim.x + threadIdx.x;
    if (i >= NN * 12) return;
    int node = i / 12;
    int v = i - node * 12;
    g_h[i] = emb4[an[node] * 12 + v];
    g_agg[i] = make_float4(0.f, 0.f, 0.f, 0.f);
}

__device__ __forceinline__ void scatter48(float* aggp, const u64 a[24]) {
#pragma unroll
    for (int v = 0; v < 6; v++) {
        float2 p0 = unpack2(a[4 * v + 0]);
        float2 p1 = unpack2(a[4 * v + 1]);
        float2 p2 = unpack2(a[4 * v + 2]);
        float2 p3 = unpack2(a[4 * v + 3]);
        asm volatile("red.global.add.v4.f32 [%0], {%1, %2, %3, %4};"
                     :: "l"(aggp + 8 * v), "f"(p0.x), "f"(p0.y), "f"(p1.x), "f"(p1.y) : "memory");
        asm volatile("red.global.add.v4.f32 [%0], {%1, %2, %3, %4};"
                     :: "l"(aggp + 8 * v + 4), "f"(p2.x), "f"(p2.y), "f"(p3.x), "f"(p3.y) : "memory");
    }
}

// SMEM (floats): [0:256) esrc ints, [256:512) edst ints, [512: +256*49) x rows.
// Edge el -> row ((el&1)<<7)+(el>>1): phase-2 thread t owns rows t, t+128
// = edges 2t, 2t+1 (consecutive after dst-sort).
#define OFF_X 512
#define EDGE_SMEM_FLOATS (OFF_X + EPC * XSTRIDE)   // 13056 floats ~ 52 KB
#define UPD_SMEM_FLOATS  (EPC * XSTRIDE)           // 12544 floats ~ 50 KB

__global__ __launch_bounds__(128, 4) void edge_kernel(int unused) {
    extern __shared__ __align__(16) float s[];
    int* esrc = (int*)s;
    int* edst = (int*)(s + 256);
    float* xs = s + OFF_X;
    int tid = threadIdx.x;

    // Stage edge ids coalescedly.
    int e_base = blockIdx.x * EPC;
#pragma unroll
    for (int i = tid; i < EPC; i += 128) {
        esrc[i] = g_ssrc[e_base + i];
        edst[i] = g_sdst[e_base + i];
    }
    __syncthreads();

    // Phase 1: coalesced gather, 4 lanes per edge (ids via broadcast LDS).
#pragma unroll
    for (int it = 0; it < 8; it++) {
        int idx = it * 128 + tid;      // 0..1023
        int el = idx >> 2;             // local edge 0..255
        int ch = idx & 3;              // chunk 0..3
        int sn = esrc[el];
        int dn = edst[el];
        const float4* hs = (const float4*)&g_h[sn * 12] + ch * 3;
        const float4* hd = (const float4*)&g_h[dn * 12] + ch * 3;
        int row = ((el & 1) << 7) + (el >> 1);
        float* xrow = xs + row * XSTRIDE + ch * 12;
#pragma unroll
        for (int i = 0; i < 3; i++) {
            float4 a = hs[i];
            float4 b = hd[i];
            xrow[4 * i + 0] = a.x * b.x;
            xrow[4 * i + 1] = a.y * b.y;
            xrow[4 * i + 2] = a.z * b.z;
            xrow[4 * i + 3] = a.w * b.w;
        }
    }
    __syncthreads();

    // Phase 2: dual consecutive edges 2t, 2t+1; weights from constant.
    float* x0 = xs + tid * XSTRIDE;
    float* x1 = xs + (tid + 128) * XSTRIDE;

    {
        u64 a0[24], a1[24];
        gemm48_dual_c(x0, x1, a0, a1, c_all, 0, 4608);
        relu_writeback(x0, a0);
        relu_writeback(x1, a1);
    }

    u64 a0[24], a1[24];
    gemm48_dual_c(x0, x1, a0, a1, c_all, 2304, 4656);

    int dst0 = edst[2 * tid];
    int dst1 = edst[2 * tid + 1];
    if (dst0 == dst1) {
#pragma unroll
        for (int j = 0; j < 24; j++) a0[j] = add2(a0[j], a1[j]);
        scatter48((float*)&g_agg[dst0 * 12], a0);
    } else {
        scatter48((float*)&g_agg[dst0 * 12], a0);
        scatter48((float*)&g_agg[dst1 * 12], a1);
    }
}

// Dual-node update kernel: constant weights (upper half of c_all).
__global__ __launch_bounds__(128, 3) void update_kernel(int unused) {
    extern __shared__ __align__(16) float s[];
    float* xs = s;
    int tid = threadIdx.x;

    int n_base = blockIdx.x * 256;
    const float4 z = make_float4(0.f, 0.f, 0.f, 0.f);
#pragma unroll
    for (int it = 0; it < 8; it++) {
        int idx = it * 128 + tid;
        int nl = idx >> 2;
        int ch = idx & 3;
        int n = n_base + nl;
        if (n < NN) {
            float4* ap = &g_agg[n * 12] + ch * 3;
            int row = ((nl & 1) << 7) + (nl >> 1);
            float* xrow = xs + row * XSTRIDE + ch * 12;
#pragma unroll
            for (int i = 0; i < 3; i++) {
                float4 a = ap[i];
                xrow[4 * i + 0] = a.x;
                xrow[4 * i + 1] = a.y;
                xrow[4 * i + 2] = a.z;
                xrow[4 * i + 3] = a.w;
                ap[i] = z;  // reset for next layer's scatter
            }
        }
    }
    __syncthreads();

    int n0 = n_base + 2 * tid;
    if (n0 >= NN) return;
    int n1 = n0 + 1;

    float* x0 = xs + tid * XSTRIDE;
    float* x1 = xs + (tid + 128) * XSTRIDE;

    {
        u64 a0[24], a1[24];
        gemm48_dual_c(x0, x1, a0, a1, c_all, 4704 + 0, 4704 + 4608);
        relu_writeback(x0, a0);
        relu_writeback(x1, a1);
    }

    u64 a0[24], a1[24];
    gemm48_dual_c(x0, x1, a0, a1, c_all, 4704 + 2304, 4704 + 4656);

    {
        float4* hp = &g_h[n0 * 12];
#pragma unroll
        for (int v = 0; v < 12; v++) {
            float2 p0 = unpack2(a0[2 * v]);
            float2 p1 = unpack2(a0[2 * v + 1]);
            float4 h = hp[v];
            h.x += p0.x; h.y += p0.y; h.z += p1.x; h.w += p1.y;
            hp[v] = h;
        }
    }
    if (n1 < NN) {
        float4* hp = &g_h[n1 * 12];
#pragma unroll
        for (int v = 0; v < 12; v++) {
            float2 p0 = unpack2(a1[2 * v]);
            float2 p1 = unpack2(a1[2 * v + 1]);
            float4 h = hp[v];
            h.x += p0.x; h.y += p0.y; h.z += p1.x; h.w += p1.y;
            hp[v] = h;
        }
    }
}

// Readout from constant: c_all holds [0:2304) rw1, [2304:2352) rb1,
// [2352:2400) rw2, [2400] rb2 at this point (copied after the conv loop).
__global__ __launch_bounds__(256, 2) void readout_kernel(
    const int* __restrict__ gid, float* __restrict__ out) {
    int n = blockIdx.x * 256 + threadIdx.x;
    if (n >= NN) return;

    const float4* hp = &g_h[n * 12];
    float x[D];
#pragma unroll
    for (int v = 0; v < 12; v++) {
        float4 a = hp[v];
        x[4 * v + 0] = a.x;
        x[4 * v + 1] = a.y;
        x[4 * v + 2] = a.z;
        x[4 * v + 3] = a.w;
    }

    float y = c_all[2400];
#pragma unroll 1
    for (int half = 0; half < 2; half++) {
        u64 acc[12];
#pragma unroll
        for (int j = 0; j < 12; j++)
            acc[j] = *reinterpret_cast<const u64*>(&c_all[2304 + half * 24 + 2 * j]);
#pragma unroll 4
        for (int k = 0; k < D; k++) {
            u64 xk = pack2(x[k], x[k]);
            const ulonglong2* wr = reinterpret_cast<const ulonglong2*>(&c_all[k * D + half * 24]);
#pragma unroll
            for (int jj = 0; jj < 6; jj++) {
                ulonglong2 w = wr[jj];
                acc[2 * jj]     = fma2(xk, w.x, acc[2 * jj]);
                acc[2 * jj + 1] = fma2(xk, w.y, acc[2 * jj + 1]);
            }
        }
#pragma unroll
        for (int j = 0; j < 12; j++) {
            float2 v = unpack2(acc[j]);
            y += fmaxf(v.x, 0.f) * c_all[2352 + half * 24 + 2 * j];
            y += fmaxf(v.y, 0.f) * c_all[2352 + half * 24 + 2 * j + 1];
        }
    }

    atomicAdd(&out[gid[n]], y);
}

extern "C" void kernel_launch(void* const* d_in, const int* in_sizes, int n_in,
                              void* d_out, int out_size) {
    const int*   an   = (const int*)d_in[0];
    const int*   edge = (const int*)d_in[1];
    const int*   gid  = (const int*)d_in[2];
    const float* emb  = (const float*)d_in[3];
    const float* mw1  = (const float*)d_in[4];
    const float* mb1  = (const float*)d_in[5];
    const float* mw2  = (const float*)d_in[6];
    const float* mb2  = (const float*)d_in[7];
    const float* uw1  = (const float*)d_in[8];
    const float* ub1  = (const float*)d_in[9];
    const float* uw2  = (const float*)d_in[10];
    const float* ub2  = (const float*)d_in[11];
    const float* rw1  = (const float*)d_in[12];
    const float* rb1  = (const float*)d_in[13];
    const float* rw2  = (const float*)d_in[14];
    const float* rb2  = (const float*)d_in[15];
    float* out = (float*)d_out;

    const int edge_smem = EDGE_SMEM_FLOATS * (int)sizeof(float);  // ~52 KB
    const int upd_smem  = UPD_SMEM_FLOATS * (int)sizeof(float);   // ~50 KB
    cudaFuncSetAttribute(edge_kernel, cudaFuncAttributeMaxDynamicSharedMemorySize, edge_smem);
    cudaFuncSetAttribute(update_kernel, cudaFuncAttributeMaxDynamicSharedMemorySize, upd_smem);

    // Host-side device addresses of staging symbols (no-work queries).
    void *pp = nullptr, *pr = nullptr;
    cudaGetSymbolAddress(&pp, g_pack);
    cudaGetSymbolAddress(&pr, g_packr);

    // Pack all layers' weights contiguously (one kernel).
    pack_weights_kernel<<<(NCONVS * 9408 + 255) / 256, 256>>>(mw1, mb1, mw2, mb2,
                                                              uw1, ub1, uw2, ub2,
                                                              rw1, rb1, rw2, rb2);

    // counting sort of edges by dst (edge list constant across layers)
    zero_cnt_kernel<<<(NN + 255) / 256, 256>>>();
    hist_kernel<<<(NE + 255) / 256, 256>>>(edge);
    scan1_kernel<<<NSCAN_BLKS, SCAN_BLK>>>();
    scan2_kernel<<<1, 32>>>();
    scan3_kernel<<<(NN + 255) / 256, 256>>>();
    scatter_sort_kernel<<<(NE + 255) / 256, 256>>>(edge);

    embed_kernel<<<(NN * 12 + 255) / 256, 256>>>(an, (const float4*)emb);

    for (int l = 0; l < NCONVS; l++) {
        cudaMemcpyToSymbolAsync(c_all, (const float*)pp + l * 9408, 9408 * sizeof(float), 0,
                                cudaMemcpyDeviceToDevice);
        edge_kernel<<<NE / EPC, 128, edge_smem>>>(0);
        update_kernel<<<(NN + 255) / 256, 128, upd_smem>>>(0);
    }

    // Swap in readout weights, then readout.
    cudaMemcpyToSymbolAsync(c_all, pr, 2401 * sizeof(float), 0, cudaMemcpyDeviceToDevice);
    cudaMemsetAsync(out, 0, NG * sizeof(float));
    readout_kernel<<<(NN + 255) / 256, 256>>>(gid, out);
}